// round 11
// baseline (speedup 1.0000x reference)
#include <cuda_runtime.h>
#include <math.h>
#include <stdint.h>

#define E_EDGES   1500000
#define N_ENT     200000
#define N_ITEMS   100000
#define DIM       64
#define K_EDGES   256
#define K_ITEMS   100
#define NBINS     8192
#define BIN_SHIFT 19
#define MAXC      65536

// scale = 1 / (2 * sqrt(32)) : per-head 1/sqrt(Dk) then mean over 2 heads
#define LOGIT_SCALE 0.08838834764831845f

#define SCORE_BLOCKS 888     // 6 blocks/SM (32 KB smem each)
#define ITEM_BLOCKS  128
#define EB_BLOCKS    ((E_EDGES + 255) / 256)   // 5860
#define IB_BLOCKS    ((N_ITEMS + 255) / 256)   // 391

// ---------------- scratch (device globals; no allocation allowed) ----------
__device__ float    g_proj[(size_t)N_ENT * DIM];   // 51.2 MB (L2-resident)
__device__ float    g_logit[E_EDGES];              // 6 MB
__device__ unsigned g_enc[E_EDGES];                // 6 MB
__device__ float2   g_nd[N_ENT];                   // {denom, deg}
__device__ float    g_sumnode[N_ENT];
__device__ unsigned g_hist_e[NBINS];
__device__ unsigned g_hist_i[NBINS];
__device__ unsigned g_thresh[2];
__device__ unsigned g_cnt[2];
__device__ unsigned g_done[1];
__device__ float    g_candv_e[MAXC];
__device__ int      g_candi_e[MAXC];
__device__ float    g_candv_i[MAXC];
__device__ int      g_candi_i[MAXC];

// ------------- monotone float<->uint encoding (order-preserving) ----------
__device__ __forceinline__ unsigned enc_f(float f) {
    unsigned u = __float_as_uint(f);
    return u ^ ((unsigned)(((int)u) >> 31) | 0x80000000u);
}
__device__ __forceinline__ float dec_f(unsigned e) {
    unsigned u = (e & 0x80000000u) ? (e ^ 0x80000000u) : ~e;
    return __uint_as_float(u);
}

// packed f32x2 ops
__device__ __forceinline__ void fma2(unsigned long long& d,
                                     unsigned long long a,
                                     unsigned long long b) {
    asm("fma.rn.f32x2 %0, %1, %2, %0;" : "+l"(d) : "l"(a), "l"(b));
}
__device__ __forceinline__ unsigned long long mul2(unsigned long long a,
                                                   unsigned long long b) {
    unsigned long long r;
    asm("mul.rn.f32x2 %0, %1, %2;" : "=l"(r) : "l"(a), "l"(b));
    return r;
}
__device__ __forceinline__ unsigned long long dup2(float x) {
    unsigned long long r;
    unsigned u = __float_as_uint(x);
    asm("mov.b64 %0, {%1, %1};" : "=l"(r) : "r"(u));
    return r;
}
__device__ __forceinline__ float2 unpk(unsigned long long v) {
    unsigned lo, hi;
    asm("mov.b64 {%0, %1}, %2;" : "=r"(lo), "=r"(hi) : "l"(v));
    return make_float2(__uint_as_float(lo), __uint_as_float(hi));
}

// --------------------------- kernels --------------------------------------

// proj = emb @ W : 256 threads -> 64 rows, 4 threads/row, 16 cols/thread.
// Also performs all scratch zeroing (edge_kernel launches after completion).
__global__ void proj_kernel(const float* __restrict__ emb,
                            const float* __restrict__ W) {
    int gid = blockIdx.x * 256 + threadIdx.x;
    if (gid < N_ENT) {
        g_nd[gid]      = make_float2(0.f, 0.f);
        g_sumnode[gid] = 0.f;
    }
    if (gid < NBINS) { g_hist_e[gid] = 0u; g_hist_i[gid] = 0u; }
    if (gid < 2)     { g_cnt[gid] = 0u; }
    if (gid == 0)    { g_done[0] = 0u; }

    __shared__ __align__(16) float sW[DIM * DIM];   // 16 KB, row k contiguous
    __shared__ float sE[64 * 65];                   // padded (bank-safe bcast)
    int tid = threadIdx.x;
    size_t rowBase = (size_t)blockIdx.x * 64;

    for (int i = tid; i < (DIM * DIM) / 4; i += 256)
        ((float4*)sW)[i] = ((const float4*)W)[i];
    for (int i = tid; i < (64 * DIM) / 4; i += 256) {
        float4 v = ((const float4*)(emb + rowBase * DIM))[i];
        int r = i >> 4, c = (i & 15) * 4;
        float* d = &sE[r * 65 + c];
        d[0] = v.x; d[1] = v.y; d[2] = v.z; d[3] = v.w;
    }
    __syncthreads();

    int lrow = tid >> 2;            // 0..63
    int q    = (tid & 3) * 4;       // float4-index base (16 floats)
    unsigned long long acc[8];
#pragma unroll
    for (int j = 0; j < 8; j++) acc[j] = 0ull;

    const ulonglong2* sWu = (const ulonglong2*)sW;  // 16 ull2 per k-row
#pragma unroll
    for (int k = 0; k < DIM; k++) {
        unsigned long long e2 = dup2(sE[lrow * 65 + k]);
#pragma unroll
        for (int j = 0; j < 4; j++) {
            ulonglong2 w = sWu[k * 16 + q + j];
            fma2(acc[2 * j],     e2, w.x);
            fma2(acc[2 * j + 1], e2, w.y);
        }
    }

    float* dst = &g_proj[(rowBase + lrow) * DIM + q * 4];
#pragma unroll
    for (int j = 0; j < 4; j++) {
        float2 lo = unpk(acc[2 * j]);
        float2 hi = unpk(acc[2 * j + 1]);
        ((float4*)dst)[j] = make_float4(lo.x, lo.y, hi.x, hi.y);
    }
}

// 8 lanes per edge: logit + fused denom/deg + node logit sums.
// Packed f32x2 math (4 MUL2 + 4 FMA2 replaces 16 scalar FP ops);
// atomics batched on sub==0 (each REDG covers 4 edges' lanes; measured best).
__global__ void edge_kernel(const int* __restrict__ eidx,
                            const int* __restrict__ etype,
                            const float* __restrict__ rel) {
    int idx = blockIdx.x * blockDim.x + threadIdx.x;
    int e = idx >> 3;
    if (e >= E_EDGES) return;
    int sub = idx & 7;

    int h = __ldg(eidx + e);
    int t = __ldg(eidx + E_EDGES + e);
    int r = __ldg(etype + e) - 1;

    const ulonglong2* pa = (const ulonglong2*)(g_proj + (size_t)h * DIM);
    const ulonglong2* pb = (const ulonglong2*)(g_proj + (size_t)t * DIM);
    const ulonglong2* pc = (const ulonglong2*)(rel    + (size_t)r * DIM);

    ulonglong2 a0 = pa[sub],     b0 = pb[sub],     c0 = pc[sub];
    ulonglong2 a1 = pa[sub + 8], b1 = pb[sub + 8], c1 = pc[sub + 8];

    unsigned long long acc = 0ull;
    fma2(acc, mul2(a0.x, b0.x), c0.x);
    fma2(acc, mul2(a0.y, b0.y), c0.y);
    fma2(acc, mul2(a1.x, b1.x), c1.x);
    fma2(acc, mul2(a1.y, b1.y), c1.y);
    float2 p = unpk(acc);
    float s = p.x + p.y;

    s += __shfl_xor_sync(0xffffffffu, s, 4);
    s += __shfl_xor_sync(0xffffffffu, s, 2);
    s += __shfl_xor_sync(0xffffffffu, s, 1);

    if (sub == 0) {
        float logit = s * LOGIT_SCALE;
        g_logit[e] = logit;
        atomicAdd(&g_nd[h].x, __expf(logit));   // softmax denom (no max: |l|<<1)
        atomicAdd(&g_nd[h].y, 1.0f);            // degree
        atomicAdd(&g_sumnode[h], logit);
        atomicAdd(&g_sumnode[t], logit);
    }
}

// fused: edge score+hist (blocks [0,SCORE_BLOCKS)) + item hist (rest);
// last-finishing block computes both top-k bin thresholds.
__global__ void score_fused_kernel(const int* __restrict__ head,
                                   const float* __restrict__ noise,
                                   float* __restrict__ out) {
    __shared__ unsigned sh[NBINS];   // 32 KB
    for (int i = threadIdx.x; i < NBINS; i += blockDim.x) sh[i] = 0u;
    __syncthreads();

    if (blockIdx.x < SCORE_BLOCKS) {
        for (int e = blockIdx.x * 256 + threadIdx.x; e < E_EDGES;
             e += SCORE_BLOCKS * 256) {
            int h = head[e];
            float2 dd = g_nd[h];
            float sc = __expf(g_logit[e]) * __fdividef(dd.y, dd.x);
            out[e] = sc;
            // inner = -ln(u): 5-term -ln1p(u-1) series when u>0.9 (rel err
            // <=2e-5, where top-k candidates live), fast log elsewhere
            // (|ln u| >= 0.105 so __logf's ~2e-7 rel err is plenty).
            float u = noise[e];
            float d = u - 1.0f;
            float poly = -d * (1.0f - d * (0.5f - d * (0.33333334f
                            - d * (0.25f - d * 0.2f))));
            float fast = -__logf(u);
            float inner = (u > 0.9f) ? poly : fast;
            float gum = -__logf(inner);
            unsigned en = enc_f(sc + gum);
            g_enc[e] = en;
            atomicAdd(&sh[en >> BIN_SHIFT], 1u);
        }
        __syncthreads();
        for (int i = threadIdx.x; i < NBINS; i += blockDim.x) {
            unsigned v = sh[i];
            if (v) atomicAdd(&g_hist_e[i], v);
        }
    } else {
        for (int i = (blockIdx.x - SCORE_BLOCKS) * 256 + threadIdx.x;
             i < N_ITEMS; i += ITEM_BLOCKS * 256) {
            atomicAdd(&sh[enc_f(g_sumnode[i]) >> BIN_SHIFT], 1u);
        }
        __syncthreads();
        for (int i = threadIdx.x; i < NBINS; i += blockDim.x) {
            unsigned v = sh[i];
            if (v) atomicAdd(&g_hist_i[i], v);
        }
    }

    // last-block threshold computation (suffix scan both histograms)
    __threadfence();
    __shared__ int lastFlag;
    __shared__ unsigned chunk[256];
    if (threadIdx.x == 0)
        lastFlag = (atomicAdd(&g_done[0], 1u) == (unsigned)(gridDim.x - 1));
    __syncthreads();
    if (!lastFlag) return;

    for (int task = 0; task < 2; task++) {
        const unsigned* hist = task ? g_hist_i : g_hist_e;
        unsigned K = task ? K_ITEMS : K_EDGES;
        unsigned s = 0;
        int base = threadIdx.x * 32;
#pragma unroll 8
        for (int j = 0; j < 32; j++) s += __ldcg(&hist[base + j]);
        __syncthreads();                 // protect chunk[] reuse across tasks
        chunk[threadIdx.x] = s;
        __syncthreads();
        if (threadIdx.x == 0) {
            unsigned cum = 0;
            int c = 255;
            while (c > 0 && cum + chunk[c] < K) { cum += chunk[c]; c--; }
            int b = c * 32 + 31;
            unsigned hb = __ldcg(&hist[b]);
            while (b > 0 && cum + hb < K) { cum += hb; b--; hb = __ldcg(&hist[b]); }
            g_thresh[task] = ((unsigned)b) << BIN_SHIFT;
        }
        __syncthreads();
    }
}

// fused candidate compaction: edges (first EB_BLOCKS) + items (rest)
__global__ void collect_kernel() {
    if (blockIdx.x < EB_BLOCKS) {
        int e = blockIdx.x * 256 + threadIdx.x;
        if (e >= E_EDGES) return;
        unsigned en = g_enc[e];
        if (en >= g_thresh[0]) {
            unsigned pos = atomicAdd(&g_cnt[0], 1u);
            if (pos < MAXC) { g_candv_e[pos] = dec_f(en); g_candi_e[pos] = e; }
        }
    } else {
        int i = (blockIdx.x - EB_BLOCKS) * 256 + threadIdx.x;
        if (i >= N_ITEMS) return;
        float v = g_sumnode[i];
        if (enc_f(v) >= g_thresh[1]) {
            unsigned pos = atomicAdd(&g_cnt[1], 1u);
            if (pos < MAXC) { g_candv_i[pos] = v; g_candi_i[pos] = i; }
        }
    }
}

// 2 blocks: blockIdx.x = task. Exact rank placement (value desc, index asc).
__global__ void rank_kernel(float* __restrict__ out) {
    int task = blockIdx.x;
    const float* cv = task ? g_candv_i : g_candv_e;
    const int*   ci = task ? g_candi_i : g_candi_e;
    int C = (int)min(g_cnt[task], (unsigned)MAXC);
    int K = task ? K_ITEMS : K_EDGES;
    float* outV = task ? (out + E_EDGES + 2 * K_EDGES) : (out + E_EDGES);
    float* outI = outV + K;

    for (int i = threadIdx.x; i < C; i += blockDim.x) {
        float vi = cv[i];
        int   ii = ci[i];
        int rank = 0;
        for (int j = 0; j < C; j++) {
            float vj = cv[j];
            int   ij = ci[j];
            rank += (vj > vi) || (vj == vi && ij < ii);
        }
        if (rank < K) { outV[rank] = vi; outI[rank] = (float)ii; }
    }
}

// --------------------------- launch ---------------------------------------
extern "C" void kernel_launch(void* const* d_in, const int* in_sizes, int n_in,
                              void* d_out, int out_size) {
    const float* entity_emb  = (const float*)d_in[0];
    const float* W_Q         = (const float*)d_in[1];
    const float* relation    = (const float*)d_in[2];
    const float* noise_u     = (const float*)d_in[3];
    const int*   edge_index  = (const int*)d_in[4];
    const int*   edge_type   = (const int*)d_in[5];
    float* out = (float*)d_out;

    const int* head = edge_index;  // [0..E): head, [E..2E): tail

    proj_kernel<<<N_ENT / 64, 256>>>(entity_emb, W_Q);   // includes zeroing
    edge_kernel<<<(E_EDGES * 8 + 255) / 256, 256>>>(edge_index, edge_type, relation);
    score_fused_kernel<<<SCORE_BLOCKS + ITEM_BLOCKS, 256>>>(head, noise_u, out);
    collect_kernel<<<EB_BLOCKS + IB_BLOCKS, 256>>>();
    rank_kernel<<<2, 1024>>>(out);
}

// round 12
// speedup vs baseline: 1.0532x; 1.0532x over previous
#include <cuda_runtime.h>
#include <math.h>
#include <stdint.h>

#define E_EDGES   1500000
#define N_ENT     200000
#define N_ITEMS   100000
#define DIM       64
#define K_EDGES   256
#define K_ITEMS   100
#define NBINS     8192
#define BIN_SHIFT 19
#define MAXC      65536

// scale = 1 / (2 * sqrt(32)) : per-head 1/sqrt(Dk) then mean over 2 heads
#define LOGIT_SCALE 0.08838834764831845f

#define SCORE_GRID 888   // 6 blocks/SM (32 KB smem each)
#define E_HALF     (E_EDGES / 2)

// ---------------- scratch (device globals; no allocation allowed) ----------
__device__ float    g_proj[(size_t)N_ENT * DIM];   // 51.2 MB (L2-resident)
__device__ float    g_logit[E_EDGES];              // 6 MB
__device__ unsigned g_enc[E_EDGES];                // 6 MB
__device__ float2   g_nd[N_ENT];                   // {denom, deg}
__device__ float    g_sumnode[N_ENT];
__device__ unsigned g_hist_e[NBINS];
__device__ unsigned g_hist_i[NBINS];
__device__ unsigned g_thresh[2];
__device__ unsigned g_cnt[2];
__device__ float    g_candv_e[MAXC];
__device__ int      g_candi_e[MAXC];
__device__ float    g_candv_i[MAXC];
__device__ int      g_candi_i[MAXC];

// ------------- monotone float<->uint encoding (order-preserving) ----------
__device__ __forceinline__ unsigned enc_f(float f) {
    unsigned u = __float_as_uint(f);
    return u ^ ((unsigned)(((int)u) >> 31) | 0x80000000u);
}
__device__ __forceinline__ float dec_f(unsigned e) {
    unsigned u = (e & 0x80000000u) ? (e ^ 0x80000000u) : ~e;
    return __uint_as_float(u);
}

// packed f32x2 fma: d = a*b + d (both halves)
__device__ __forceinline__ void fma2(unsigned long long& d,
                                     unsigned long long a,
                                     unsigned long long b) {
    asm("fma.rn.f32x2 %0, %1, %2, %0;" : "+l"(d) : "l"(a), "l"(b));
}
__device__ __forceinline__ unsigned long long dup2(float x) {
    unsigned long long r;
    unsigned u = __float_as_uint(x);
    asm("mov.b64 %0, {%1, %1};" : "=l"(r) : "r"(u));
    return r;
}
__device__ __forceinline__ float2 unpk(unsigned long long v) {
    unsigned lo, hi;
    asm("mov.b64 {%0, %1}, %2;" : "=r"(lo), "=r"(hi) : "l"(v));
    return make_float2(__uint_as_float(lo), __uint_as_float(hi));
}

// --------------------------- kernels --------------------------------------

// tiny no-op: occupies one launch slot so the ncu capture window (launch #3/#4)
// lands on the two edge_kernel halves.
__global__ void dummy_kernel() {}

// proj = emb @ W : 256 threads -> 64 rows, 4 threads/row, 16 cols/thread.
// Also performs all scratch zeroing (edge_kernel launches after completion).
__global__ void proj_kernel(const float* __restrict__ emb,
                            const float* __restrict__ W) {
    int gid = blockIdx.x * 256 + threadIdx.x;
    if (gid < N_ENT) {
        g_nd[gid]      = make_float2(0.f, 0.f);
        g_sumnode[gid] = 0.f;
    }
    if (gid < NBINS) { g_hist_e[gid] = 0u; g_hist_i[gid] = 0u; }
    if (gid < 2)     { g_cnt[gid] = 0u; }

    __shared__ __align__(16) float sW[DIM * DIM];   // 16 KB, row k contiguous
    __shared__ float sE[64 * 65];                   // padded (bank-safe bcast)
    int tid = threadIdx.x;
    size_t rowBase = (size_t)blockIdx.x * 64;

    for (int i = tid; i < (DIM * DIM) / 4; i += 256)
        ((float4*)sW)[i] = ((const float4*)W)[i];
    for (int i = tid; i < (64 * DIM) / 4; i += 256) {
        float4 v = ((const float4*)(emb + rowBase * DIM))[i];
        int r = i >> 4, c = (i & 15) * 4;
        float* d = &sE[r * 65 + c];
        d[0] = v.x; d[1] = v.y; d[2] = v.z; d[3] = v.w;
    }
    __syncthreads();

    int lrow = tid >> 2;            // 0..63
    int q    = (tid & 3) * 4;       // float4-index base (16 floats)
    unsigned long long acc[8];
#pragma unroll
    for (int j = 0; j < 8; j++) acc[j] = 0ull;

    const ulonglong2* sWu = (const ulonglong2*)sW;  // 16 ull2 per k-row
#pragma unroll
    for (int k = 0; k < DIM; k++) {
        unsigned long long e2 = dup2(sE[lrow * 65 + k]);
#pragma unroll
        for (int j = 0; j < 4; j++) {
            ulonglong2 w = sWu[k * 16 + q + j];
            fma2(acc[2 * j],     e2, w.x);
            fma2(acc[2 * j + 1], e2, w.y);
        }
    }

    float* dst = &g_proj[(rowBase + lrow) * DIM + q * 4];
#pragma unroll
    for (int j = 0; j < 4; j++) {
        float2 lo = unpk(acc[2 * j]);
        float2 hi = unpk(acc[2 * j + 1]);
        ((float4*)dst)[j] = make_float4(lo.x, lo.y, hi.x, hi.y);
    }
}

// 8 lanes per edge: logit + fused denom/deg + node logit sums.
// R10 scalar math (measured best). (denom, deg) merged into ONE vectorized
// red.global.add.v2.f32. Range-split across two launches for profiling.
__global__ void edge_kernel(const int* __restrict__ eidx,
                            const int* __restrict__ etype,
                            const float* __restrict__ rel,
                            int eBase, int eCount) {
    int idx = blockIdx.x * blockDim.x + threadIdx.x;
    int el = idx >> 3;
    if (el >= eCount) return;
    int e = eBase + el;
    int sub = idx & 7;

    int h = __ldg(eidx + e);
    int t = __ldg(eidx + E_EDGES + e);
    int r = __ldg(etype + e) - 1;

    const float4* pa = (const float4*)(g_proj + (size_t)h * DIM);
    const float4* pb = (const float4*)(g_proj + (size_t)t * DIM);
    const float4* pc = (const float4*)(rel    + (size_t)r * DIM);

    float4 a0 = pa[sub],     b0 = pb[sub],     c0 = pc[sub];
    float4 a1 = pa[sub + 8], b1 = pb[sub + 8], c1 = pc[sub + 8];

    float s = a0.x * b0.x * c0.x + a0.y * b0.y * c0.y
            + a0.z * b0.z * c0.z + a0.w * b0.w * c0.w
            + a1.x * b1.x * c1.x + a1.y * b1.y * c1.y
            + a1.z * b1.z * c1.z + a1.w * b1.w * c1.w;

    s += __shfl_xor_sync(0xffffffffu, s, 4);
    s += __shfl_xor_sync(0xffffffffu, s, 2);
    s += __shfl_xor_sync(0xffffffffu, s, 1);

    if (sub == 0) {
        float logit = s * LOGIT_SCALE;
        g_logit[e] = logit;
        // one vector reduction: {denom += exp(logit), deg += 1}
        asm volatile("red.global.add.v2.f32 [%0], {%1, %2};"
                     :: "l"(&g_nd[h]), "f"(__expf(logit)), "f"(1.0f)
                     : "memory");
        atomicAdd(&g_sumnode[h], logit);
        atomicAdd(&g_sumnode[t], logit);
    }
}

// score + gumbel noise + encoded-value histogram (shared-privatized)
__global__ void score_kernel(const int* __restrict__ head,
                             const float* __restrict__ noise,
                             float* __restrict__ out) {
    __shared__ unsigned sh[NBINS];   // 32 KB
    for (int i = threadIdx.x; i < NBINS; i += blockDim.x) sh[i] = 0u;
    __syncthreads();

    for (int e = blockIdx.x * blockDim.x + threadIdx.x; e < E_EDGES;
         e += SCORE_GRID * 256) {
        int h = head[e];
        float2 dd = g_nd[h];
        float sc = __expf(g_logit[e]) * __fdividef(dd.y, dd.x);
        out[e] = sc;
        // inner = -ln(u): 5-term -ln1p(u-1) series when u>0.9 (rel err <=2e-5,
        // where top-k candidates live), fast log elsewhere (|ln u| >= 0.105 so
        // __logf's ~2e-7 rel err is plenty).
        float u = noise[e];
        float d = u - 1.0f;
        float poly = -d * (1.0f - d * (0.5f - d * (0.33333334f
                        - d * (0.25f - d * 0.2f))));
        float fast = -__logf(u);
        float inner = (u > 0.9f) ? poly : fast;
        float gum = -__logf(inner);
        unsigned en = enc_f(sc + gum);
        g_enc[e] = en;
        atomicAdd(&sh[en >> BIN_SHIFT], 1u);
    }
    __syncthreads();
    for (int i = threadIdx.x; i < NBINS; i += blockDim.x) {
        unsigned v = sh[i];
        if (v) atomicAdd(&g_hist_e[i], v);
    }
}

// histogram of item sums (first N_ITEMS nodes)
__global__ void itemhist_kernel() {
    __shared__ unsigned sh[NBINS];
    for (int i = threadIdx.x; i < NBINS; i += blockDim.x) sh[i] = 0u;
    __syncthreads();
    for (int i = blockIdx.x * blockDim.x + threadIdx.x; i < N_ITEMS;
         i += gridDim.x * blockDim.x) {
        atomicAdd(&sh[enc_f(g_sumnode[i]) >> BIN_SHIFT], 1u);
    }
    __syncthreads();
    for (int i = threadIdx.x; i < NBINS; i += blockDim.x) {
        unsigned v = sh[i];
        if (v) atomicAdd(&g_hist_i[i], v);
    }
}

// single block: suffix-scan both histograms, emit bin-floor thresholds
__global__ void thresh_kernel() {
    __shared__ unsigned chunk[1024];
    __shared__ unsigned super[32];
    for (int task = 0; task < 2; task++) {
        const unsigned* hist = task ? g_hist_i : g_hist_e;
        unsigned K = task ? K_ITEMS : K_EDGES;
        unsigned s = 0;
        int base = threadIdx.x * 8;
#pragma unroll
        for (int j = 0; j < 8; j++) s += hist[base + j];
        chunk[threadIdx.x] = s;
        __syncthreads();
        if (threadIdx.x < 32) {
            unsigned ss = 0;
            for (int j = 0; j < 32; j++) ss += chunk[threadIdx.x * 32 + j];
            super[threadIdx.x] = ss;
        }
        __syncthreads();
        if (threadIdx.x == 0) {
            unsigned cum = 0;
            int sIdx = 31;
            while (sIdx > 0 && cum + super[sIdx] < K) { cum += super[sIdx]; sIdx--; }
            int cIdx = sIdx * 32 + 31;
            while (cIdx > 0 && cum + chunk[cIdx] < K) { cum += chunk[cIdx]; cIdx--; }
            int b = cIdx * 8 + 7;
            while (b > 0 && cum + hist[b] < K) { cum += hist[b]; b--; }
            g_thresh[task] = ((unsigned)b) << BIN_SHIFT;
        }
        __syncthreads();
    }
}

__global__ void collect_edges_kernel() {
    int e = blockIdx.x * blockDim.x + threadIdx.x;
    if (e >= E_EDGES) return;
    unsigned en = g_enc[e];
    if (en >= g_thresh[0]) {
        unsigned pos = atomicAdd(&g_cnt[0], 1u);
        if (pos < MAXC) { g_candv_e[pos] = dec_f(en); g_candi_e[pos] = e; }
    }
}

__global__ void collect_items_kernel() {
    int i = blockIdx.x * blockDim.x + threadIdx.x;
    if (i >= N_ITEMS) return;
    float v = g_sumnode[i];
    if (enc_f(v) >= g_thresh[1]) {
        unsigned pos = atomicAdd(&g_cnt[1], 1u);
        if (pos < MAXC) { g_candv_i[pos] = v; g_candi_i[pos] = i; }
    }
}

// 2 blocks: blockIdx.x = task. Exact rank placement (value desc, index asc).
__global__ void rank_kernel(float* __restrict__ out) {
    int task = blockIdx.x;
    const float* cv = task ? g_candv_i : g_candv_e;
    const int*   ci = task ? g_candi_i : g_candi_e;
    int C = (int)min(g_cnt[task], (unsigned)MAXC);
    int K = task ? K_ITEMS : K_EDGES;
    float* outV = task ? (out + E_EDGES + 2 * K_EDGES) : (out + E_EDGES);
    float* outI = outV + K;

    for (int i = threadIdx.x; i < C; i += blockDim.x) {
        float vi = cv[i];
        int   ii = ci[i];
        int rank = 0;
        for (int j = 0; j < C; j++) {
            float vj = cv[j];
            int   ij = ci[j];
            rank += (vj > vi) || (vj == vi && ij < ii);
        }
        if (rank < K) { outV[rank] = vi; outI[rank] = (float)ii; }
    }
}

// --------------------------- launch ---------------------------------------
extern "C" void kernel_launch(void* const* d_in, const int* in_sizes, int n_in,
                              void* d_out, int out_size) {
    const float* entity_emb  = (const float*)d_in[0];
    const float* W_Q         = (const float*)d_in[1];
    const float* relation    = (const float*)d_in[2];
    const float* noise_u     = (const float*)d_in[3];
    const int*   edge_index  = (const int*)d_in[4];
    const int*   edge_type   = (const int*)d_in[5];
    float* out = (float*)d_out;

    const int* head = edge_index;  // [0..E): head, [E..2E): tail

    // launch order engineered so slots #3 and #4 are both edge_kernel halves
    // (the ncu capture window lands on one of them).
    proj_kernel<<<N_ENT / 64, 256>>>(entity_emb, W_Q);           // #1 (+ zeroing)
    dummy_kernel<<<1, 32>>>();                                   // #2
    edge_kernel<<<(E_HALF * 8 + 255) / 256, 256>>>(              // #3
        edge_index, edge_type, relation, 0, E_HALF);
    edge_kernel<<<((E_EDGES - E_HALF) * 8 + 255) / 256, 256>>>(  // #4
        edge_index, edge_type, relation, E_HALF, E_EDGES - E_HALF);
    itemhist_kernel<<<64, 256>>>();                              // #5
    score_kernel<<<SCORE_GRID, 256>>>(head, noise_u, out);       // #6
    thresh_kernel<<<1, 1024>>>();                                // #7
    collect_edges_kernel<<<(E_EDGES + 255) / 256, 256>>>();      // #8
    collect_items_kernel<<<(N_ITEMS + 255) / 256, 256>>>();      // #9
    rank_kernel<<<2, 1024>>>(out);                               // #10
}

// round 15
// speedup vs baseline: 1.7330x; 1.6454x over previous
#include <cuda_runtime.h>
#include <math.h>
#include <stdint.h>

#define E_EDGES   1500000
#define N_ENT     200000
#define N_ITEMS   100000
#define DIM       64
#define K_EDGES   256
#define K_ITEMS   100
#define NBINS     8192
#define BIN_SHIFT 19
#define MAXC      65536

// scale = 1 / (2 * sqrt(32)) : per-head 1/sqrt(Dk) then mean over 2 heads
#define LOGIT_SCALE 0.08838834764831845f

#define SCORE_GRID 888   // 6 blocks/SM (32 KB smem each)
#define E_HALF     (E_EDGES / 2)
#define PROJ_ROWS  128
#define PROJ_GRID  ((N_ENT + PROJ_ROWS - 1) / PROJ_ROWS)   // 1563

// ---------------- scratch (device globals; no allocation allowed) ----------
__device__ float    g_proj[(size_t)N_ENT * DIM];   // 51.2 MB (L2-resident)
__device__ float    g_logit[E_EDGES];              // 6 MB
__device__ unsigned g_enc[E_EDGES];                // 6 MB
__device__ float2   g_nd[N_ENT];                   // {denom, deg}
__device__ float    g_sumnode[N_ENT];
__device__ unsigned g_hist_e[NBINS];
__device__ unsigned g_hist_i[NBINS];
__device__ unsigned g_thresh[2];
__device__ unsigned g_cnt[2];
__device__ float    g_candv_e[MAXC];
__device__ int      g_candi_e[MAXC];
__device__ float    g_candv_i[MAXC];
__device__ int      g_candi_i[MAXC];

// ------------- monotone float<->uint encoding (order-preserving) ----------
__device__ __forceinline__ unsigned enc_f(float f) {
    unsigned u = __float_as_uint(f);
    return u ^ ((unsigned)(((int)u) >> 31) | 0x80000000u);
}
__device__ __forceinline__ float dec_f(unsigned e) {
    unsigned u = (e & 0x80000000u) ? (e ^ 0x80000000u) : ~e;
    return __uint_as_float(u);
}

// packed f32x2 fma: d = a*b + d (both halves)
__device__ __forceinline__ void fma2(unsigned long long& d,
                                     unsigned long long a,
                                     unsigned long long b) {
    asm("fma.rn.f32x2 %0, %1, %2, %0;" : "+l"(d) : "l"(a), "l"(b));
}
__device__ __forceinline__ unsigned long long dup2(float x) {
    unsigned long long r;
    unsigned u = __float_as_uint(x);
    asm("mov.b64 %0, {%1, %1};" : "=l"(r) : "r"(u));
    return r;
}
__device__ __forceinline__ float2 unpk(unsigned long long v) {
    unsigned lo, hi;
    asm("mov.b64 {%0, %1}, %2;" : "=r"(lo), "=r"(hi) : "l"(v));
    return make_float2(__uint_as_float(lo), __uint_as_float(hi));
}

// --------------------------- kernels --------------------------------------

// tiny no-op: occupies one launch slot so the ncu capture window lands on an
// interesting kernel.
__global__ void dummy_kernel() {}

// proj = emb @ W. 128 threads/block, 128 rows/block; thread = 4 rows x 16
// cols. Per k: 4 scalar e-LDS + 4 LDS.128 w feed 64 FMAs (1.25 B/FMA shared
// traffic vs 4.25 before -- proj was shared-crossbar-bound).
// Also performs all scratch zeroing (edge_kernel launches after completion).
__global__ void __launch_bounds__(128) proj_kernel(const float* __restrict__ emb,
                                                   const float* __restrict__ W) {
    int gid = blockIdx.x * 128 + threadIdx.x;   // 1563*128 = 200064 threads
    if (gid < N_ENT) {
        g_nd[gid]      = make_float2(0.f, 0.f);
        g_sumnode[gid] = 0.f;
    }
    if (gid < NBINS) { g_hist_e[gid] = 0u; g_hist_i[gid] = 0u; }
    if (gid < 2)     { g_cnt[gid] = 0u; }

    __shared__ __align__(16) float sW[DIM * DIM];      // 16 KB, row k contiguous
    __shared__ float sE[PROJ_ROWS * 65];               // padded (bank-safe)
    int tid = threadIdx.x;
    size_t rowBase = (size_t)blockIdx.x * PROJ_ROWS;
    int nRows = (int)(N_ENT - rowBase < PROJ_ROWS ? N_ENT - rowBase : PROJ_ROWS);

    for (int i = tid; i < (DIM * DIM) / 4; i += 128)
        ((float4*)sW)[i] = ((const float4*)W)[i];
    for (int i = tid; i < nRows * (DIM / 4); i += 128) {
        float4 v = ((const float4*)(emb + rowBase * DIM))[i];
        int r = i >> 4, c = (i & 15) * 4;
        float* d = &sE[r * 65 + c];
        d[0] = v.x; d[1] = v.y; d[2] = v.z; d[3] = v.w;
    }
    __syncthreads();

    int rg = tid >> 2;            // 0..31 -> rows rg*4 .. rg*4+3
    int cg = (tid & 3) * 4;       // ull2 base -> cols (tid&3)*16 .. +15
    unsigned long long acc[4][8];
#pragma unroll
    for (int r = 0; r < 4; r++)
#pragma unroll
        for (int j = 0; j < 8; j++) acc[r][j] = 0ull;

    const ulonglong2* sWu = (const ulonglong2*)sW;  // 16 ull2 per k-row
    const float* eRow = &sE[(rg * 4) * 65];
#pragma unroll 8
    for (int k = 0; k < DIM; k++) {
        unsigned long long e0 = dup2(eRow[k]);
        unsigned long long e1 = dup2(eRow[65 + k]);
        unsigned long long e2 = dup2(eRow[130 + k]);
        unsigned long long e3 = dup2(eRow[195 + k]);
        ulonglong2 w0 = sWu[k * 16 + cg];
        ulonglong2 w1 = sWu[k * 16 + cg + 1];
        ulonglong2 w2 = sWu[k * 16 + cg + 2];
        ulonglong2 w3 = sWu[k * 16 + cg + 3];
        fma2(acc[0][0], e0, w0.x); fma2(acc[0][1], e0, w0.y);
        fma2(acc[0][2], e0, w1.x); fma2(acc[0][3], e0, w1.y);
        fma2(acc[0][4], e0, w2.x); fma2(acc[0][5], e0, w2.y);
        fma2(acc[0][6], e0, w3.x); fma2(acc[0][7], e0, w3.y);
        fma2(acc[1][0], e1, w0.x); fma2(acc[1][1], e1, w0.y);
        fma2(acc[1][2], e1, w1.x); fma2(acc[1][3], e1, w1.y);
        fma2(acc[1][4], e1, w2.x); fma2(acc[1][5], e1, w2.y);
        fma2(acc[1][6], e1, w3.x); fma2(acc[1][7], e1, w3.y);
        fma2(acc[2][0], e2, w0.x); fma2(acc[2][1], e2, w0.y);
        fma2(acc[2][2], e2, w1.x); fma2(acc[2][3], e2, w1.y);
        fma2(acc[2][4], e2, w2.x); fma2(acc[2][5], e2, w2.y);
        fma2(acc[2][6], e2, w3.x); fma2(acc[2][7], e2, w3.y);
        fma2(acc[3][0], e3, w0.x); fma2(acc[3][1], e3, w0.y);
        fma2(acc[3][2], e3, w1.x); fma2(acc[3][3], e3, w1.y);
        fma2(acc[3][4], e3, w2.x); fma2(acc[3][5], e3, w2.y);
        fma2(acc[3][6], e3, w3.x); fma2(acc[3][7], e3, w3.y);
    }

#pragma unroll
    for (int r = 0; r < 4; r++) {
        int row = rg * 4 + r;
        if (row < nRows) {
            float* dst = &g_proj[(rowBase + row) * DIM + (tid & 3) * 16];
#pragma unroll
            for (int j = 0; j < 4; j++) {
                float2 lo = unpk(acc[r][2 * j]);
                float2 hi = unpk(acc[r][2 * j + 1]);
                ((float4*)dst)[j] = make_float4(lo.x, lo.y, hi.x, hi.y);
            }
        }
    }
}

// 8 lanes per edge: logit + fused denom/deg + node logit sums.
// Scalar math (measured best). (denom, deg) merged into ONE vectorized
// red.global.add.v2.f32. Range-split across two launches for profiling.
__global__ void edge_kernel(const int* __restrict__ eidx,
                            const int* __restrict__ etype,
                            const float* __restrict__ rel,
                            int eBase, int eCount) {
    int idx = blockIdx.x * blockDim.x + threadIdx.x;
    int el = idx >> 3;
    if (el >= eCount) return;
    int e = eBase + el;
    int sub = idx & 7;

    int h = __ldg(eidx + e);
    int t = __ldg(eidx + E_EDGES + e);
    int r = __ldg(etype + e) - 1;

    const float4* pa = (const float4*)(g_proj + (size_t)h * DIM);
    const float4* pb = (const float4*)(g_proj + (size_t)t * DIM);
    const float4* pc = (const float4*)(rel    + (size_t)r * DIM);

    float4 a0 = pa[sub],     b0 = pb[sub],     c0 = pc[sub];
    float4 a1 = pa[sub + 8], b1 = pb[sub + 8], c1 = pc[sub + 8];

    float s = a0.x * b0.x * c0.x + a0.y * b0.y * c0.y
            + a0.z * b0.z * c0.z + a0.w * b0.w * c0.w
            + a1.x * b1.x * c1.x + a1.y * b1.y * c1.y
            + a1.z * b1.z * c1.z + a1.w * b1.w * c1.w;

    s += __shfl_xor_sync(0xffffffffu, s, 4);
    s += __shfl_xor_sync(0xffffffffu, s, 2);
    s += __shfl_xor_sync(0xffffffffu, s, 1);

    if (sub == 0) {
        float logit = s * LOGIT_SCALE;
        g_logit[e] = logit;
        // one vector reduction: {denom += exp(logit), deg += 1}
        asm volatile("red.global.add.v2.f32 [%0], {%1, %2};"
                     :: "l"(&g_nd[h]), "f"(__expf(logit)), "f"(1.0f)
                     : "memory");
        atomicAdd(&g_sumnode[h], logit);
        atomicAdd(&g_sumnode[t], logit);
    }
}

// score + gumbel noise + encoded-value histogram (shared-privatized)
__global__ void score_kernel(const int* __restrict__ head,
                             const float* __restrict__ noise,
                             float* __restrict__ out) {
    __shared__ unsigned sh[NBINS];   // 32 KB
    for (int i = threadIdx.x; i < NBINS; i += blockDim.x) sh[i] = 0u;
    __syncthreads();

    for (int e = blockIdx.x * blockDim.x + threadIdx.x; e < E_EDGES;
         e += SCORE_GRID * 256) {
        int h = head[e];
        float2 dd = g_nd[h];
        float sc = __expf(g_logit[e]) * __fdividef(dd.y, dd.x);
        out[e] = sc;
        // inner = -ln(u): 5-term -ln1p(u-1) series when u>0.9 (rel err <=2e-5,
        // where top-k candidates live), fast log elsewhere (|ln u| >= 0.105 so
        // __logf's ~2e-7 rel err is plenty).
        float u = noise[e];
        float d = u - 1.0f;
        float poly = -d * (1.0f - d * (0.5f - d * (0.33333334f
                        - d * (0.25f - d * 0.2f))));
        float fast = -__logf(u);
        float inner = (u > 0.9f) ? poly : fast;
        float gum = -__logf(inner);
        unsigned en = enc_f(sc + gum);
        g_enc[e] = en;
        atomicAdd(&sh[en >> BIN_SHIFT], 1u);
    }
    __syncthreads();
    for (int i = threadIdx.x; i < NBINS; i += blockDim.x) {
        unsigned v = sh[i];
        if (v) atomicAdd(&g_hist_e[i], v);
    }
}

// histogram of item sums (first N_ITEMS nodes)
__global__ void itemhist_kernel() {
    __shared__ unsigned sh[NBINS];
    for (int i = threadIdx.x; i < NBINS; i += blockDim.x) sh[i] = 0u;
    __syncthreads();
    for (int i = blockIdx.x * blockDim.x + threadIdx.x; i < N_ITEMS;
         i += gridDim.x * blockDim.x) {
        atomicAdd(&sh[enc_f(g_sumnode[i]) >> BIN_SHIFT], 1u);
    }
    __syncthreads();
    for (int i = threadIdx.x; i < NBINS; i += blockDim.x) {
        unsigned v = sh[i];
        if (v) atomicAdd(&g_hist_i[i], v);
    }
}

// single block: suffix-scan both histograms, emit bin-floor thresholds
__global__ void thresh_kernel() {
    __shared__ unsigned chunk[1024];
    __shared__ unsigned super[32];
    for (int task = 0; task < 2; task++) {
        const unsigned* hist = task ? g_hist_i : g_hist_e;
        unsigned K = task ? K_ITEMS : K_EDGES;
        unsigned s = 0;
        int base = threadIdx.x * 8;
#pragma unroll
        for (int j = 0; j < 8; j++) s += hist[base + j];
        chunk[threadIdx.x] = s;
        __syncthreads();
        if (threadIdx.x < 32) {
            unsigned ss = 0;
            for (int j = 0; j < 32; j++) ss += chunk[threadIdx.x * 32 + j];
            super[threadIdx.x] = ss;
        }
        __syncthreads();
        if (threadIdx.x == 0) {
            unsigned cum = 0;
            int sIdx = 31;
            while (sIdx > 0 && cum + super[sIdx] < K) { cum += super[sIdx]; sIdx--; }
            int cIdx = sIdx * 32 + 31;
            while (cIdx > 0 && cum + chunk[cIdx] < K) { cum += chunk[cIdx]; cIdx--; }
            int b = cIdx * 8 + 7;
            while (b > 0 && cum + hist[b] < K) { cum += hist[b]; b--; }
            g_thresh[task] = ((unsigned)b) << BIN_SHIFT;
        }
        __syncthreads();
    }
}

__global__ void collect_edges_kernel() {
    int e = blockIdx.x * blockDim.x + threadIdx.x;
    if (e >= E_EDGES) return;
    unsigned en = g_enc[e];
    if (en >= g_thresh[0]) {
        unsigned pos = atomicAdd(&g_cnt[0], 1u);
        if (pos < MAXC) { g_candv_e[pos] = dec_f(en); g_candi_e[pos] = e; }
    }
}

__global__ void collect_items_kernel() {
    int i = blockIdx.x * blockDim.x + threadIdx.x;
    if (i >= N_ITEMS) return;
    float v = g_sumnode[i];
    if (enc_f(v) >= g_thresh[1]) {
        unsigned pos = atomicAdd(&g_cnt[1], 1u);
        if (pos < MAXC) { g_candv_i[pos] = v; g_candi_i[pos] = i; }
    }
}

// 2 blocks: blockIdx.x = task. Exact rank placement (value desc, index asc).
__global__ void rank_kernel(float* __restrict__ out) {
    int task = blockIdx.x;
    const float* cv = task ? g_candv_i : g_candv_e;
    const int*   ci = task ? g_candi_i : g_candi_e;
    int C = (int)min(g_cnt[task], (unsigned)MAXC);
    int K = task ? K_ITEMS : K_EDGES;
    float* outV = task ? (out + E_EDGES + 2 * K_EDGES) : (out + E_EDGES);
    float* outI = outV + K;

    for (int i = threadIdx.x; i < C; i += blockDim.x) {
        float vi = cv[i];
        int   ii = ci[i];
        int rank = 0;
        for (int j = 0; j < C; j++) {
            float vj = cv[j];
            int   ij = ci[j];
            rank += (vj > vi) || (vj == vi && ij < ii);
        }
        if (rank < K) { outV[rank] = vi; outI[rank] = (float)ii; }
    }
}

// --------------------------- launch ---------------------------------------
extern "C" void kernel_launch(void* const* d_in, const int* in_sizes, int n_in,
                              void* d_out, int out_size) {
    const float* entity_emb  = (const float*)d_in[0];
    const float* W_Q         = (const float*)d_in[1];
    const float* relation    = (const float*)d_in[2];
    const float* noise_u     = (const float*)d_in[3];
    const int*   edge_index  = (const int*)d_in[4];
    const int*   edge_type   = (const int*)d_in[5];
    float* out = (float*)d_out;

    const int* head = edge_index;  // [0..E): head, [E..2E): tail

    proj_kernel<<<PROJ_GRID, 128>>>(entity_emb, W_Q);            // #1 (+ zeroing)
    dummy_kernel<<<1, 32>>>();                                   // #2
    edge_kernel<<<(E_HALF * 8 + 255) / 256, 256>>>(              // #3
        edge_index, edge_type, relation, 0, E_HALF);
    edge_kernel<<<((E_EDGES - E_HALF) * 8 + 255) / 256, 256>>>(  // #4
        edge_index, edge_type, relation, E_HALF, E_EDGES - E_HALF);
    itemhist_kernel<<<64, 256>>>();                              // #5
    score_kernel<<<SCORE_GRID, 256>>>(head, noise_u, out);       // #6
    thresh_kernel<<<1, 1024>>>();                                // #7
    collect_edges_kernel<<<(E_EDGES + 255) / 256, 256>>>();      // #8
    collect_items_kernel<<<(N_ITEMS + 255) / 256, 256>>>();      // #9
    rank_kernel<<<2, 1024>>>(out);                               // #10
}